// round 1
// baseline (speedup 1.0000x reference)
#include <cuda_runtime.h>

#define LL 9
#define BB 4
#define CC 512
#define HW 1024

// ---------------- scratch (device globals; no allocation) ----------------
__device__ __align__(16) float g_invq[LL*BB*HW];
__device__ __align__(16) float g_invs[LL*BB*HW];
__device__ __align__(16) float g_corr[(size_t)BB*HW*HW];   // 16 MB, reused as attn
__device__ __align__(16) float g_c1[BB*256*HW];            // conv1 out [b][256][32*32]
__device__ __align__(16) float g_c2[BB*256*900];           // conv2 out [b][256][30*30]
__device__ __align__(16) float g_pool[BB*256*100];         // pooled [b][256][10*10]
__device__ __align__(16) float g_wt1[9*1024*256];          // w1 transposed [tap][ic][oc]
__device__ __align__(16) float g_wt2[9*256*256];           // w2 transposed [tap][ic][oc]
__device__ __align__(16) float g_nq2[BB*HW];
__device__ __align__(16) float g_na2[BB*HW];

// ---------------- helpers ----------------
__device__ __forceinline__ void fma44(float (&acc)[4][4], float4 a, float4 b) {
    acc[0][0] = fmaf(a.x, b.x, acc[0][0]); acc[0][1] = fmaf(a.x, b.y, acc[0][1]);
    acc[0][2] = fmaf(a.x, b.z, acc[0][2]); acc[0][3] = fmaf(a.x, b.w, acc[0][3]);
    acc[1][0] = fmaf(a.y, b.x, acc[1][0]); acc[1][1] = fmaf(a.y, b.y, acc[1][1]);
    acc[1][2] = fmaf(a.y, b.z, acc[1][2]); acc[1][3] = fmaf(a.y, b.w, acc[1][3]);
    acc[2][0] = fmaf(a.z, b.x, acc[2][0]); acc[2][1] = fmaf(a.z, b.y, acc[2][1]);
    acc[2][2] = fmaf(a.z, b.z, acc[2][2]); acc[2][3] = fmaf(a.z, b.w, acc[2][3]);
    acc[3][0] = fmaf(a.w, b.x, acc[3][0]); acc[3][1] = fmaf(a.w, b.y, acc[3][1]);
    acc[3][2] = fmaf(a.w, b.z, acc[3][2]); acc[3][3] = fmaf(a.w, b.w, acc[3][3]);
}

// ---------------- weight transposes: w[oc][ic][tap] -> wt[tap][ic][oc] ----------------
__global__ void k_twt1(const float* __restrict__ w1) {
    int i = blockIdx.x * 256 + threadIdx.x;          // < 256*1024*9 = 2359296
    float v = w1[i];
    int oc = i / 9216; int r = i % 9216; int ic = r / 9; int tap = r % 9;
    g_wt1[tap * 262144 + ic * 256 + oc] = v;
}
__global__ void k_twt2(const float* __restrict__ w2) {
    int i = blockIdx.x * 256 + threadIdx.x;          // < 256*256*9 = 589824
    float v = w2[i];
    int oc = i / 2304; int r = i % 2304; int ic = r / 9; int tap = r % 9;
    g_wt2[tap * 65536 + ic * 256 + oc] = v;
}

// ---------------- per-level per-pixel inverse channel norms ----------------
__global__ void k_norms(const float* __restrict__ fq, const float* __restrict__ fs) {
    int lb  = blockIdx.y;                             // 0..35 (l*B+b)
    int pix = blockIdx.x * 256 + threadIdx.x;         // 0..1023
    const float* src = (blockIdx.z == 0 ? fq : fs) + (size_t)lb * CC * HW + pix;
    float ss = 0.f;
#pragma unroll 8
    for (int c = 0; c < CC; c++) { float v = src[(size_t)c * HW]; ss = fmaf(v, v, ss); }
    float inv = 1.0f / fmaxf(sqrtf(ss), 1e-12f);
    (blockIdx.z == 0 ? g_invq : g_invs)[lb * HW + pix] = inv;
}

// ---------------- corr: sum_l relu( (fq_l . fs_l) * invq * invs ) ----------------
// Per (l,b): C[m,n] = sum_k A[k,m]*B[k,n], A,B stored [512][1024] (K-major).
__global__ void k_corr(const float* __restrict__ fq, const float* __restrict__ fs) {
    __shared__ __align__(16) float As[16][64];
    __shared__ __align__(16) float Bs[16][64];
    int b  = blockIdx.z;
    int m0 = blockIdx.y * 64, n0 = blockIdx.x * 64;
    int tid = threadIdx.x, tx = tid & 15, ty = tid >> 4;
    int kk = (tid * 4) >> 6, mm = (tid * 4) & 63;     // load coords (4 consecutive mm)

    float tot[4][4];
#pragma unroll
    for (int i = 0; i < 4; i++)
#pragma unroll
        for (int j = 0; j < 4; j++) tot[i][j] = 0.f;

    for (int l = 0; l < LL; l++) {
        const float* A  = fq + (size_t)(l * BB + b) * CC * HW;
        const float* Bp = fs + (size_t)(l * BB + b) * CC * HW;
        float acc[4][4];
#pragma unroll
        for (int i = 0; i < 4; i++)
#pragma unroll
            for (int j = 0; j < 4; j++) acc[i][j] = 0.f;

        for (int kt = 0; kt < 32; kt++) {
            int k0 = kt * 16;
            float4 av = *(const float4*)(A  + (size_t)(k0 + kk) * HW + m0 + mm);
            float4 bv = *(const float4*)(Bp + (size_t)(k0 + kk) * HW + n0 + mm);
            *(float4*)&As[kk][mm] = av;
            *(float4*)&Bs[kk][mm] = bv;
            __syncthreads();
#pragma unroll
            for (int k2 = 0; k2 < 16; k2++) {
                float4 a4 = *(const float4*)&As[k2][ty * 4];
                float4 b4 = *(const float4*)&Bs[k2][tx * 4];
                fma44(acc, a4, b4);
            }
            __syncthreads();
        }
        const float* iq = g_invq + (l * BB + b) * HW + m0 + ty * 4;
        const float* is = g_invs + (l * BB + b) * HW + n0 + tx * 4;
        float qv[4], sv[4];
#pragma unroll
        for (int i = 0; i < 4; i++) { qv[i] = iq[i]; sv[i] = is[i]; }
#pragma unroll
        for (int i = 0; i < 4; i++)
#pragma unroll
            for (int j = 0; j < 4; j++)
                tot[i][j] += fmaxf(acc[i][j] * qv[i] * sv[j], 0.f);
    }

    float* outp = g_corr + (size_t)b * HW * HW + (size_t)m0 * HW + n0;
#pragma unroll
    for (int i = 0; i < 4; i++) {
        float4 o = make_float4(tot[i][0], tot[i][1], tot[i][2], tot[i][3]);
        *(float4*)(outp + (size_t)(ty * 4 + i) * HW + tx * 4) = o;
    }
}

// ---------------- row softmax (scale = TEMP/L folds the mean) ----------------
__global__ void k_softmax() {
    float* r = g_corr + (size_t)blockIdx.x * HW;      // blockIdx.x = b*1024 + q
    int tid = threadIdx.x, wid = tid >> 5, lane = tid & 31;
    const float sc = 20.0f / 9.0f;
    float4 v = ((const float4*)r)[tid];
    v.x *= sc; v.y *= sc; v.z *= sc; v.w *= sc;
    float mx = fmaxf(fmaxf(v.x, v.y), fmaxf(v.z, v.w));
#pragma unroll
    for (int o = 16; o; o >>= 1) mx = fmaxf(mx, __shfl_xor_sync(0xffffffffu, mx, o));
    __shared__ float sh[8];
    if (lane == 0) sh[wid] = mx;
    __syncthreads();
    float m = sh[0];
#pragma unroll
    for (int k = 1; k < 8; k++) m = fmaxf(m, sh[k]);
    v.x = __expf(v.x - m); v.y = __expf(v.y - m);
    v.z = __expf(v.z - m); v.w = __expf(v.w - m);
    float s = v.x + v.y + v.z + v.w;
#pragma unroll
    for (int o = 16; o; o >>= 1) s += __shfl_xor_sync(0xffffffffu, s, o);
    __syncthreads();
    if (lane == 0) sh[wid] = s;
    __syncthreads();
    float tot = 0.f;
#pragma unroll
    for (int k = 0; k < 8; k++) tot += sh[k];
    float inv = 1.0f / tot;
    v.x *= inv; v.y *= inv; v.z *= inv; v.w *= inv;
    ((float4*)r)[tid] = v;
}

// ---------------- att_fq[b,c,q] = sum_s attn[b,q,s] * f_s[b,c,s]  (NT gemm) ----------------
__global__ void k_att(const float* __restrict__ fs_in, float* __restrict__ attout) {
    __shared__ __align__(16) float As[16][68];
    __shared__ __align__(16) float Bs[16][68];
    int b  = blockIdx.z;
    int m0 = blockIdx.y * 64;   // c
    int n0 = blockIdx.x * 64;   // q
    int tid = threadIdx.x, tx = tid & 15, ty = tid >> 4;
    int lm = tid >> 2, lk = (tid & 3) * 4;            // 64 rows, 4 k each

    const float* A  = fs_in + (size_t)b * CC * HW;    // [512][1024] row-major (k=s contig)
    const float* Bm = g_corr + (size_t)b * HW * HW;   // attn [1024][1024] (k=s contig)

    float acc[4][4];
#pragma unroll
    for (int i = 0; i < 4; i++)
#pragma unroll
        for (int j = 0; j < 4; j++) acc[i][j] = 0.f;

    for (int kt = 0; kt < 64; kt++) {
        int k0 = kt * 16;
        float4 a4 = *(const float4*)(A  + (size_t)(m0 + lm) * HW + k0 + lk);
        float4 b4 = *(const float4*)(Bm + (size_t)(n0 + lm) * HW + k0 + lk);
        As[lk + 0][lm] = a4.x; As[lk + 1][lm] = a4.y; As[lk + 2][lm] = a4.z; As[lk + 3][lm] = a4.w;
        Bs[lk + 0][lm] = b4.x; Bs[lk + 1][lm] = b4.y; Bs[lk + 2][lm] = b4.z; Bs[lk + 3][lm] = b4.w;
        __syncthreads();
#pragma unroll
        for (int k2 = 0; k2 < 16; k2++) {
            float4 av = *(const float4*)&As[k2][ty * 4];
            float4 bv = *(const float4*)&Bs[k2][tx * 4];
            fma44(acc, av, bv);
        }
        __syncthreads();
    }
    float* outp = attout + (size_t)b * CC * HW + (size_t)m0 * HW + n0;
#pragma unroll
    for (int i = 0; i < 4; i++) {
        float4 o = make_float4(acc[i][0], acc[i][1], acc[i][2], acc[i][3]);
        *(float4*)(outp + (size_t)(ty * 4 + i) * HW + tx * 4) = o;
    }
}

// ---------------- inverse channel norms of f_q and att_fq ----------------
__global__ void k_norm2(const float* __restrict__ f_q, const float* __restrict__ att) {
    int b   = blockIdx.y;
    int pix = blockIdx.x * 256 + threadIdx.x;
    const float* src = (blockIdx.z == 0 ? f_q : att) + (size_t)b * CC * HW + pix;
    float ss = 0.f;
#pragma unroll 8
    for (int c = 0; c < CC; c++) { float v = src[(size_t)c * HW]; ss = fmaf(v, v, ss); }
    float inv = 1.0f / fmaxf(sqrtf(ss), 1e-12f);
    (blockIdx.z == 0 ? g_nq2 : g_na2)[b * HW + pix] = inv;
}

// ---------------- fq = l2n(f_q) + 0.5*l2n(att_fq) ----------------
__global__ void k_fqout(const float* __restrict__ f_q, const float* __restrict__ att,
                        float* __restrict__ fqo) {
    int i4 = blockIdx.x * 256 + threadIdx.x;          // < 524288
    int base = i4 * 4;
    int b = base >> 19;                               // 524288 = 2^19 per batch
    int pix = base & 1023;
    float4 q = ((const float4*)f_q)[i4];
    float4 a = ((const float4*)att)[i4];
    int ni = (b * HW + pix) >> 2;
    float4 nq = ((const float4*)g_nq2)[ni];
    float4 na = ((const float4*)g_na2)[ni];
    float4 o;
    o.x = q.x * nq.x + a.x * na.x * 0.5f;
    o.y = q.y * nq.y + a.y * na.y * 0.5f;
    o.z = q.z * nq.z + a.z * na.z * 0.5f;
    o.w = q.w * nq.w + a.w * na.w * 0.5f;
    ((float4*)fqo)[i4] = o;
}

// ---------------- conv1: implicit GEMM, input concat(f_q,f_s), dil=2, pad=2, +bias, relu ----------------
__global__ void k_conv1(const float* __restrict__ f_q, const float* __restrict__ f_s,
                        const float* __restrict__ b1) {
    __shared__ __align__(16) float Ws[16][64];
    __shared__ __align__(16) float Is[16][64];
    int b = blockIdx.z, oc0 = blockIdx.y * 64, n0 = blockIdx.x * 64;
    int tid = threadIdx.x, tx = tid & 15, ty = tid >> 4;
    int kk = (tid * 4) >> 6, nn0 = (tid * 4) & 63;
    const float* fqp = f_q + (size_t)b * CC * HW;
    const float* fsp = f_s + (size_t)b * CC * HW;

    int py[4], px[4];
#pragma unroll
    for (int j = 0; j < 4; j++) { int p = n0 + nn0 + j; py[j] = p >> 5; px[j] = p & 31; }

    float acc[4][4];
#pragma unroll
    for (int i = 0; i < 4; i++)
#pragma unroll
        for (int j = 0; j < 4; j++) acc[i][j] = 0.f;

    for (int tap = 0; tap < 9; tap++) {
        int dy = 2 * (tap / 3) - 2, dx = 2 * (tap % 3) - 2;
        int off[4]; bool inb[4];
#pragma unroll
        for (int j = 0; j < 4; j++) {
            int iy = py[j] + dy, ix = px[j] + dx;
            inb[j] = ((unsigned)iy < 32u) && ((unsigned)ix < 32u);
            off[j] = iy * 32 + ix;
        }
        const float* wb = g_wt1 + tap * 262144 + oc0;
        for (int ict = 0; ict < 64; ict++) {
            int ic0 = ict * 16;
            float4 wv = *(const float4*)(wb + (ic0 + kk) * 256 + nn0);
            *(float4*)&Ws[kk][nn0] = wv;
            const float* ib = (ic0 < 512 ? fqp + (size_t)ic0 * HW
                                         : fsp + (size_t)(ic0 - 512) * HW) + (size_t)kk * HW;
#pragma unroll
            for (int j = 0; j < 4; j++) Is[kk][nn0 + j] = inb[j] ? ib[off[j]] : 0.f;
            __syncthreads();
#pragma unroll
            for (int k2 = 0; k2 < 16; k2++) {
                float4 w4 = *(const float4*)&Ws[k2][ty * 4];
                float4 i4 = *(const float4*)&Is[k2][tx * 4];
                fma44(acc, w4, i4);
            }
            __syncthreads();
        }
    }
    float* outp = g_c1 + (size_t)b * 262144;
#pragma unroll
    for (int i = 0; i < 4; i++) {
        int oc = oc0 + ty * 4 + i;
        float bias = b1[oc];
        float4 o = make_float4(fmaxf(acc[i][0] + bias, 0.f), fmaxf(acc[i][1] + bias, 0.f),
                               fmaxf(acc[i][2] + bias, 0.f), fmaxf(acc[i][3] + bias, 0.f));
        *(float4*)(outp + (size_t)oc * HW + n0 + tx * 4) = o;
    }
}

// ---------------- conv2: implicit GEMM, 3x3 VALID on 32x32 -> 30x30, +bias ----------------
__global__ void k_conv2(const float* __restrict__ b2) {
    __shared__ __align__(16) float Ws[16][64];
    __shared__ __align__(16) float Is[16][64];
    int b = blockIdx.z, oc0 = blockIdx.y * 64, n0 = blockIdx.x * 64;
    int tid = threadIdx.x, tx = tid & 15, ty = tid >> 4;
    int kk = (tid * 4) >> 6, nn0 = (tid * 4) & 63;

    int py[4], px[4];
#pragma unroll
    for (int j = 0; j < 4; j++) {
        int p = n0 + nn0 + j; if (p > 899) p = 899;
        py[j] = p / 30; px[j] = p % 30;
    }

    float acc[4][4];
#pragma unroll
    for (int i = 0; i < 4; i++)
#pragma unroll
        for (int j = 0; j < 4; j++) acc[i][j] = 0.f;

    for (int tap = 0; tap < 9; tap++) {
        int dy = tap / 3, dx = tap % 3;
        int off[4];
#pragma unroll
        for (int j = 0; j < 4; j++) off[j] = (py[j] + dy) * 32 + (px[j] + dx);
        const float* wb = g_wt2 + tap * 65536 + oc0;
        for (int ict = 0; ict < 16; ict++) {
            int ic0 = ict * 16;
            float4 wv = *(const float4*)(wb + (ic0 + kk) * 256 + nn0);
            *(float4*)&Ws[kk][nn0] = wv;
            const float* ib = g_c1 + (size_t)b * 262144 + (size_t)(ic0 + kk) * HW;
#pragma unroll
            for (int j = 0; j < 4; j++) Is[kk][nn0 + j] = ib[off[j]];
            __syncthreads();
#pragma unroll
            for (int k2 = 0; k2 < 16; k2++) {
                float4 w4 = *(const float4*)&Ws[k2][ty * 4];
                float4 i4 = *(const float4*)&Is[k2][tx * 4];
                fma44(acc, w4, i4);
            }
            __syncthreads();
        }
    }
#pragma unroll
    for (int i = 0; i < 4; i++) {
        int oc = oc0 + ty * 4 + i;
        float bias = b2[oc];
#pragma unroll
        for (int j = 0; j < 4; j++) {
            int p = n0 + tx * 4 + j;
            if (p < 900) g_c2[(size_t)b * 230400 + (size_t)oc * 900 + p] = acc[i][j] + bias;
        }
    }
}

// ---------------- 3x3 stride-3 maxpool: 30x30 -> 10x10 ----------------
__global__ void k_pool() {
    int oc = blockIdx.x, b = blockIdx.y;
    int t = threadIdx.x;
    if (t >= 100) return;
    int y = t / 10, x = t % 10;
    const float* in = g_c2 + ((size_t)b * 256 + oc) * 900;
    float m = -3.4e38f;
#pragma unroll
    for (int dy = 0; dy < 3; dy++)
#pragma unroll
        for (int dx = 0; dx < 3; dx++)
            m = fmaxf(m, in[(3 * y + dy) * 30 + 3 * x + dx]);
    g_pool[((size_t)b * 256 + oc) * 100 + t] = m;
}

// ---------------- conv3 (3x3 VALID, 10x10 -> 8x8) + mean -> weight[b] ----------------
__global__ void k_conv3(const float* __restrict__ w3, const float* __restrict__ b3,
                        float* __restrict__ wout) {
    int b = blockIdx.x;
    int tid = threadIdx.x;
    int o = tid >> 2, part = tid & 3;         // 64 outputs x 4 partial sums
    int oy = o >> 3, ox = o & 7;
    float s = 0.f;
    for (int ic = part * 64; ic < part * 64 + 64; ic++) {
        const float* pp = g_pool + ((size_t)b * 256 + ic) * 100 + oy * 10 + ox;
        const float* wp = w3 + ic * 9;
#pragma unroll
        for (int ky = 0; ky < 3; ky++)
#pragma unroll
            for (int kx = 0; kx < 3; kx++)
                s = fmaf(pp[ky * 10 + kx], wp[ky * 3 + kx], s);
    }
    s += __shfl_down_sync(0xffffffffu, s, 1);
    s += __shfl_down_sync(0xffffffffu, s, 2);
    __shared__ float sh[64];
    if (part == 0) sh[o] = s;
    __syncthreads();
    if (tid < 32) {
        float v = sh[tid] + sh[tid + 32];
#pragma unroll
        for (int off = 16; off; off >>= 1) v += __shfl_xor_sync(0xffffffffu, v, off);
        if (tid == 0) wout[b] = v * (1.0f / 64.0f) + b3[0];
    }
}

// ---------------- launch ----------------
extern "C" void kernel_launch(void* const* d_in, const int* in_sizes, int n_in,
                              void* d_out, int out_size) {
    const float* fq_feats = (const float*)d_in[0];
    const float* fs_feats = (const float*)d_in[1];
    const float* f_q = (const float*)d_in[2];
    const float* f_s = (const float*)d_in[3];
    const float* w1 = (const float*)d_in[4];
    const float* b1 = (const float*)d_in[5];
    const float* w2 = (const float*)d_in[6];
    const float* b2 = (const float*)d_in[7];
    const float* w3 = (const float*)d_in[8];
    const float* b3 = (const float*)d_in[9];

    float* out     = (float*)d_out;
    float* fq_out  = out;                       // [4,512,32,32] = 2097152
    float* att_out = out + 2097152;             // [4,512,32,32]
    float* w_out   = out + 4194304;             // [1,4]

    k_twt1<<<9216, 256>>>(w1);
    k_twt2<<<2304, 256>>>(w2);
    k_norms<<<dim3(4, 36, 2), 256>>>(fq_feats, fs_feats);
    k_corr<<<dim3(16, 16, 4), 256>>>(fq_feats, fs_feats);
    k_softmax<<<4096, 256>>>();
    k_att<<<dim3(16, 8, 4), 256>>>(f_s, att_out);
    k_norm2<<<dim3(4, 4, 2), 256>>>(f_q, att_out);
    k_fqout<<<2048, 256>>>(f_q, att_out, fq_out);
    k_conv1<<<dim3(16, 4, 4), 256>>>(f_q, f_s, b1);
    k_conv2<<<dim3(15, 4, 4), 256>>>(b2);
    k_pool<<<dim3(256, 4), 128>>>();
    k_conv3<<<4, 256>>>(w3, b3, w_out);
}